// round 8
// baseline (speedup 1.0000x reference)
#include <cuda_runtime.h>
#include <cuda_bf16.h>

// Inputs (metadata order):
//   d_in[0] x                     float32 [2048]
//   d_in[1] y                     float32 [2048]
//   d_in[2] post_order_expression int32   [15]
//   d_in[3] post_level_map        int32   [15]
//   d_in[4] is_operator           bool    [5]
//   d_in[5] parameters            float32 [15,3]
// Output: float32 [D1, D2] row-major, out[i*D2 + j] = K(x[i], y[j])

#define NUM_ATOMS 3
#define MAX_NODES 15
#define EPSX 1e-6f
#define LOG2E 1.4426950408889634f
#define TWO_PI 6.283185307179586f
#define ROWS 2
#define MAGIC_RND 12582912.0f   // 1.5 * 2^23

// Raw hardware approximations — single MUFU op each, independent of
// whether the harness compiles with --use_fast_math.
__device__ __forceinline__ float ex2_fast(float x) {
    float r; asm("ex2.approx.ftz.f32 %0, %1;" : "=f"(r) : "f"(x)); return r;
}
__device__ __forceinline__ float sin_fast(float x) {
    float r; asm("sin.approx.ftz.f32 %0, %1;" : "=f"(r) : "f"(x)); return r;
}

__device__ __forceinline__ float sin2pi_frac(float h) {
    // sin(2*pi*(h - rint h)) with |h| << 2^22. Magic-constant round keeps the
    // chain on the FMA pipe (no FRND/cvt). __fadd_rn prevents folding.
    float t = __fadd_rn(h, MAGIC_RND);
    float r = __fadd_rn(t, -MAGIC_RND);
    float f = h - r;                       // [-0.5, 0.5]
    return sin_fast(TWO_PI * f);           // |arg| <= pi
}

// Generic-path compile (thread 0 -> shared). Only runs on the fallback path.
__device__ __forceinline__ void compile_prog(const int* __restrict__ pe,
                                             const int* __restrict__ pl,
                                             const float* __restrict__ params,
                                             int* s_op, float4* s_c, int* s_meta) {
    int na = 0;
    for (int i = 0; i < MAX_NODES; ++i) {
        int v = pe[i];
        if (v < 0) continue;
        float4 c = make_float4(0.f, 0.f, 0.f, 0.f);
        if (v < NUM_ATOMS) {
            int lvl = pl[i];
            float p0 = params[3 * lvl + 0];
            float p1 = params[3 * lvl + 1];
            float p2 = params[3 * lvl + 2];
            float p0s = p0 * p0;
            float p1s = p1 * p1;
            if (v == 0) {                 // rbf
                c.x = p0s;
                c.y = __fdividef(-0.5f * LOG2E, p1s + EPSX);
            } else if (v == 1) {          // linear
                c.x = p0s;
                c.y = p1s;
            } else {                      // periodic
                c.x = p0s;
                c.y = __fdividef(-2.0f * LOG2E, p1s + EPSX);
                c.z = __fdividef(0.5f, p2 * p2 + 1.0f);
            }
        }
        s_op[na] = v;
        s_c[na]  = c;
        ++na;
    }
    s_meta[0] = na;
}

// ---------------------------------------------------------------------------
// Fused kernel: ROWS=2 rows/block -> 1024 blocks (55 warps/SM offered),
// __launch_bounds__(256,6) -> 48 resident warps/SM. Warp-parallel compile:
// lane l owns node l; ballot fingerprints; shfl broadcasts the 9 constants.
// Fast path per thread: 8 y values x 2 rows = 16 elements, all
// transcendentals as raw MUFU approx ops.
//   k1 = ex2(aY*d^2 + aW); k2 = bX*x*y + bY; k3 = ex2(pY*s^2 + pW);
//   k4 = ex2(dY*d^2 + dW); out = (k4+k3) + k1*k2;  s = sin(2pi*frac(d*pZ))
// ---------------------------------------------------------------------------
__global__ void __launch_bounds__(256, 6)
tree_fused_kernel(const float* __restrict__ x,
                  const float* __restrict__ y,
                  float* __restrict__ out,
                  int d1, int d2,
                  const int* __restrict__ pe,
                  const int* __restrict__ pl,
                  const float* __restrict__ params) {
    const int t    = threadIdx.x;
    const int lane = t & 31;
    const int qcols = d2 >> 2;
    const int i0   = blockIdx.x * ROWS;

    // ---- warp-parallel compile ----
    int v = -1;
    float cx = 0.f, cy = 0.f, cz = 0.f, cw = 0.f;
    if (lane < MAX_NODES) v = __ldg(pe + lane);

    // fingerprint: nodes 0..6 == [0,1,4,2,0,3,3], nodes 7..14 inactive
    const int want7[7] = {0, 1, 4, 2, 0, 3, 3};
    bool okl = (lane < 7) ? (v == want7[lane])
             : (lane < MAX_NODES ? (v < 0) : true);
    const unsigned mask = __ballot_sync(0xffffffffu, okl);
    const bool fast = (mask == 0xffffffffu);

    if (lane < MAX_NODES && v >= 0 && v < NUM_ATOMS) {
        int   lvl = __ldg(pl + lane);
        float p0  = __ldg(params + 3 * lvl + 0);
        float p1  = __ldg(params + 3 * lvl + 1);
        float p2  = __ldg(params + 3 * lvl + 2);
        float p0s = p0 * p0;
        float p1s = p1 * p1;
        if (v == 0) {                     // rbf
            cx = p0s;
            cy = __fdividef(-0.5f * LOG2E, p1s + EPSX);
            cw = __log2f(p0s);
        } else if (v == 1) {              // linear
            cx = p0s;
            cy = p1s;
        } else {                          // periodic
            cx = p0s;
            cy = __fdividef(-2.0f * LOG2E, p1s + EPSX);
            cz = __fdividef(0.5f, p2 * p2 + 1.0f);
            cw = __log2f(p0s);
        }
    }

    const float4* y4p = reinterpret_cast<const float4*>(y);

    if (fast && qcols == 512 && blockDim.x == 256 && (i0 & 1) == 0) {
        // broadcast the 9 constants from their owning lanes
        const float aY = __shfl_sync(0xffffffffu, cy, 0);
        const float aW = __shfl_sync(0xffffffffu, cw, 0);
        const float bX = __shfl_sync(0xffffffffu, cx, 1);
        const float bY = __shfl_sync(0xffffffffu, cy, 1);
        const float pY = __shfl_sync(0xffffffffu, cy, 3);
        const float pZ = __shfl_sync(0xffffffffu, cz, 3);
        const float pW = __shfl_sync(0xffffffffu, cw, 3);
        const float dY = __shfl_sync(0xffffffffu, cy, 4);
        const float dW = __shfl_sync(0xffffffffu, cw, 4);

        const float2 x2 = __ldg(reinterpret_cast<const float2*>(x + i0));
        const float  xr[ROWS] = {x2.x, x2.y};

        const float4 ya = __ldg(y4p + t);
        const float4 yb = __ldg(y4p + t + 256);
        const float yv[8] = {ya.x, ya.y, ya.z, ya.w, yb.x, yb.y, yb.z, yb.w};

#pragma unroll
        for (int rr = 0; rr < ROWS; ++rr) {
            const float xi = xr[rr];
            float r[8];
#pragma unroll
            for (int l = 0; l < 8; ++l) {
                float yj  = yv[l];
                float d   = xi - yj;
                float d2s = d * d;
                float k1  = ex2_fast(fmaf(aY, d2s, aW));   // rbf #1
                float k2  = fmaf(bX, xi * yj, bY);         // linear
                float m   = k1 * k2;                       // mul
                float s   = sin2pi_frac(d * pZ);           // periodic
                float k3  = ex2_fast(fmaf(pY * s, s, pW));
                float k4  = ex2_fast(fmaf(dY, d2s, dW));   // rbf #2 (reuses d^2)
                r[l] = (k4 + k3) + m;                      // add, add
            }
            float4* o4p = reinterpret_cast<float4*>(out + (size_t)(i0 + rr) * d2);
            o4p[t]       = make_float4(r[0], r[1], r[2], r[3]);
            o4p[t + 256] = make_float4(r[4], r[5], r[6], r[7]);
        }
        return;
    }

    // ---- generic interpreter fallback (uniform across the whole grid) ----
    __shared__ int    s_op[MAX_NODES];
    __shared__ float4 s_c[MAX_NODES];
    __shared__ int    s_meta[1];
    if (t == 0) compile_prog(pe, pl, params, s_op, s_c, s_meta);
    __syncthreads();

    const int n = s_meta[0];
    for (int rr = 0; rr < ROWS; ++rr) {
        const int i = i0 + rr;
        if (i >= d1) break;
        const float xi = __ldg(x + i);
        float4* o4p = reinterpret_cast<float4*>(out + (size_t)i * d2);
        for (int c = t; c < qcols; c += blockDim.x) {
            const float4 y4 = __ldg(y4p + c);
            float yv[4] = {y4.x, y4.y, y4.z, y4.w};
            float dx[4];
#pragma unroll
            for (int l = 0; l < 4; ++l) dx[l] = xi - yv[l];

            float st[4][4];
#pragma unroll
            for (int l = 0; l < 4; ++l) st[0][l] = 0.0f;
            int ptr = 0;
            for (int nn = 0; nn < n; ++nn) {
                const int    op = s_op[nn];
                const float4 cc = s_c[nn];
                if (op >= NUM_ATOMS) {
                    if (op == NUM_ATOMS) {
#pragma unroll
                        for (int l = 0; l < 4; ++l)
                            st[ptr - 2][l] = st[ptr - 1][l] + st[ptr - 2][l];
                    } else {
#pragma unroll
                        for (int l = 0; l < 4; ++l)
                            st[ptr - 2][l] = st[ptr - 1][l] * st[ptr - 2][l];
                    }
                    --ptr;
                } else if (op == 0) {
#pragma unroll
                    for (int l = 0; l < 4; ++l)
                        st[ptr][l] = cc.x * ex2_fast(cc.y * dx[l] * dx[l]);
                    ++ptr;
                } else if (op == 1) {
#pragma unroll
                    for (int l = 0; l < 4; ++l)
                        st[ptr][l] = fmaf(cc.x, xi * yv[l], cc.y);
                    ++ptr;
                } else {
#pragma unroll
                    for (int l = 0; l < 4; ++l) {
                        float s = sin2pi_frac(dx[l] * cc.z);
                        st[ptr][l] = cc.x * ex2_fast(cc.y * s * s);
                    }
                    ++ptr;
                }
            }
            o4p[c] = make_float4(st[0][0], st[0][1], st[0][2], st[0][3]);
        }
    }
}

// Scalar fallback for d2 not divisible by 4 (not expected in this bench).
__global__ void tree_scalar_kernel(const float* __restrict__ x,
                                   const float* __restrict__ y,
                                   float* __restrict__ out,
                                   int d1, int d2,
                                   const int* __restrict__ pe,
                                   const int* __restrict__ pl,
                                   const float* __restrict__ params) {
    __shared__ int    s_op[MAX_NODES];
    __shared__ float4 s_c[MAX_NODES];
    __shared__ int    s_meta[1];
    if (threadIdx.x == 0) compile_prog(pe, pl, params, s_op, s_c, s_meta);
    __syncthreads();

    long idx = (long)blockIdx.x * blockDim.x + threadIdx.x;
    long total = (long)d1 * d2;
    if (idx >= total) return;
    int i = (int)(idx / d2);
    int j = (int)(idx - (long)i * d2);
    float xi = x[i], yj = y[j];
    float dx = xi - yj;
    float st[4] = {0.f, 0.f, 0.f, 0.f};
    int ptr = 0;
    const int n = s_meta[0];
    for (int nn = 0; nn < n; ++nn) {
        const int    op = s_op[nn];
        const float4 c  = s_c[nn];
        if (op >= NUM_ATOMS) {
            float v = (op == NUM_ATOMS) ? (st[ptr - 1] + st[ptr - 2])
                                        : (st[ptr - 1] * st[ptr - 2]);
            st[ptr - 2] = v; --ptr;
        } else if (op == 0) {
            st[ptr++] = c.x * ex2_fast(c.y * dx * dx);
        } else if (op == 1) {
            st[ptr++] = fmaf(c.x, xi * yj, c.y);
        } else {
            float s = sin2pi_frac(dx * c.z);
            st[ptr++] = c.x * ex2_fast(c.y * s * s);
        }
    }
    out[idx] = st[0];
}

extern "C" void kernel_launch(void* const* d_in, const int* in_sizes, int n_in,
                              void* d_out, int out_size) {
    const float* x      = (const float*)d_in[0];
    const float* y      = (const float*)d_in[1];
    const int*   pe     = (const int*)d_in[2];
    const int*   pl     = (const int*)d_in[3];
    const float* params = (const float*)d_in[5];
    float*       out    = (float*)d_out;

    const int d1 = in_sizes[0];
    const int d2 = in_sizes[1];

    if ((d2 & 3) == 0 && (d1 % ROWS) == 0) {
        tree_fused_kernel<<<d1 / ROWS, 256>>>(x, y, out, d1, d2, pe, pl, params);
    } else {
        long total = (long)d1 * d2;
        int blocks = (int)((total + 255) / 256);
        tree_scalar_kernel<<<blocks, 256>>>(x, y, out, d1, d2, pe, pl, params);
    }
}

// round 9
// speedup vs baseline: 1.0180x; 1.0180x over previous
#include <cuda_runtime.h>
#include <cuda_bf16.h>

// Inputs (metadata order):
//   d_in[0] x                     float32 [2048]
//   d_in[1] y                     float32 [2048]
//   d_in[2] post_order_expression int32   [15]
//   d_in[3] post_level_map        int32   [15]
//   d_in[4] is_operator           bool    [5]
//   d_in[5] parameters            float32 [15,3]
// Output: float32 [D1, D2] row-major, out[i*D2 + j] = K(x[i], y[j])

#define NUM_ATOMS 3
#define MAX_NODES 15
#define EPSX 1e-6f
#define LOG2E 1.4426950408889634f
#define TWO_PI 6.283185307179586f
#define ROWS 4
#define MAGIC_RND 12582912.0f   // 1.5 * 2^23

typedef unsigned long long ull;

// Raw hardware approximations — single MUFU op each.
__device__ __forceinline__ float ex2_fast(float x) {
    float r; asm("ex2.approx.ftz.f32 %0, %1;" : "=f"(r) : "f"(x)); return r;
}
__device__ __forceinline__ float sin_fast(float x) {
    float r; asm("sin.approx.ftz.f32 %0, %1;" : "=f"(r) : "f"(x)); return r;
}

// Packed f32x2 ops (FFMA2/FADD2/FMUL2 — only reachable via PTX).
__device__ __forceinline__ ull pack2(float lo, float hi) {
    ull r; asm("mov.b64 %0, {%1, %2};" : "=l"(r) : "f"(lo), "f"(hi)); return r;
}
__device__ __forceinline__ void unpack2(ull v, float& lo, float& hi) {
    asm("mov.b64 {%0, %1}, %2;" : "=f"(lo), "=f"(hi) : "l"(v));
}
__device__ __forceinline__ ull add2(ull a, ull b) {
    ull r; asm("add.rn.f32x2 %0, %1, %2;" : "=l"(r) : "l"(a), "l"(b)); return r;
}
__device__ __forceinline__ ull mul2(ull a, ull b) {
    ull r; asm("mul.rn.f32x2 %0, %1, %2;" : "=l"(r) : "l"(a), "l"(b)); return r;
}
__device__ __forceinline__ ull fma2(ull a, ull b, ull c) {
    ull r; asm("fma.rn.f32x2 %0, %1, %2, %3;" : "=l"(r) : "l"(a), "l"(b), "l"(c)); return r;
}

__device__ __forceinline__ float sin2pi_frac(float h) {
    float t = __fadd_rn(h, MAGIC_RND);
    float r = __fadd_rn(t, -MAGIC_RND);
    float f = h - r;
    return sin_fast(TWO_PI * f);
}

// Generic-path compile (thread 0 -> shared). Only runs on the fallback path.
__device__ __forceinline__ void compile_prog(const int* __restrict__ pe,
                                             const int* __restrict__ pl,
                                             const float* __restrict__ params,
                                             int* s_op, float4* s_c, int* s_meta) {
    int na = 0;
    for (int i = 0; i < MAX_NODES; ++i) {
        int v = pe[i];
        if (v < 0) continue;
        float4 c = make_float4(0.f, 0.f, 0.f, 0.f);
        if (v < NUM_ATOMS) {
            int lvl = pl[i];
            float p0 = params[3 * lvl + 0];
            float p1 = params[3 * lvl + 1];
            float p2 = params[3 * lvl + 2];
            float p0s = p0 * p0;
            float p1s = p1 * p1;
            if (v == 0) {                 // rbf
                c.x = p0s;
                c.y = __fdividef(-0.5f * LOG2E, p1s + EPSX);
            } else if (v == 1) {          // linear
                c.x = p0s;
                c.y = p1s;
            } else {                      // periodic
                c.x = p0s;
                c.y = __fdividef(-2.0f * LOG2E, p1s + EPSX);
                c.z = __fdividef(0.5f, p2 * p2 + 1.0f);
            }
        }
        s_op[na] = v;
        s_c[na]  = c;
        ++na;
    }
    s_meta[0] = na;
}

// ---------------------------------------------------------------------------
// Fused kernel: ROWS=4 rows/block, 512 threads (16 warps) -> 512 blocks,
// 2 resident blocks/SM (32 warps). Warp-parallel compile; fast path evaluates
// a 4x4 tile per thread with the FMA chain fully packed as f32x2 (FFMA2),
// halving fma-pipe issues. MUFU (3x EX2 + 1x SIN per element) binds.
//   k1 = ex2(aY*d^2 + aW); k2 = bX*x*y + bY; k3 = ex2(pY*s^2 + pW);
//   k4 = ex2(dY*d^2 + dW); out = (k4+k3) + k1*k2;  s = sin(2pi*frac(d*pZ))
// ---------------------------------------------------------------------------
__global__ void __launch_bounds__(512, 2)
tree_fused_kernel(const float* __restrict__ x,
                  const float* __restrict__ y,
                  float* __restrict__ out,
                  int d1, int d2,
                  const int* __restrict__ pe,
                  const int* __restrict__ pl,
                  const float* __restrict__ params) {
    const int t    = threadIdx.x;
    const int lane = t & 31;
    const int qcols = d2 >> 2;
    const int i0   = blockIdx.x * ROWS;

    // ---- warp-parallel compile ----
    int v = -1;
    float cx = 0.f, cy = 0.f, cz = 0.f, cw = 0.f;
    if (lane < MAX_NODES) v = __ldg(pe + lane);

    const int want7[7] = {0, 1, 4, 2, 0, 3, 3};
    bool okl = (lane < 7) ? (v == want7[lane])
             : (lane < MAX_NODES ? (v < 0) : true);
    const unsigned mask = __ballot_sync(0xffffffffu, okl);
    const bool fast = (mask == 0xffffffffu);

    if (lane < MAX_NODES && v >= 0 && v < NUM_ATOMS) {
        int   lvl = __ldg(pl + lane);
        float p0  = __ldg(params + 3 * lvl + 0);
        float p1  = __ldg(params + 3 * lvl + 1);
        float p2  = __ldg(params + 3 * lvl + 2);
        float p0s = p0 * p0;
        float p1s = p1 * p1;
        if (v == 0) {                     // rbf
            cx = p0s;
            cy = __fdividef(-0.5f * LOG2E, p1s + EPSX);
            cw = __log2f(p0s);
        } else if (v == 1) {              // linear
            cx = p0s;
            cy = p1s;
        } else {                          // periodic
            cx = p0s;
            cy = __fdividef(-2.0f * LOG2E, p1s + EPSX);
            cz = __fdividef(0.5f, p2 * p2 + 1.0f);
            cw = __log2f(p0s);
        }
    }

    const float4* y4p = reinterpret_cast<const float4*>(y);

    if (fast && qcols == (int)blockDim.x && (i0 & 3) == 0 && i0 + ROWS <= d1) {
        // broadcast the 9 constants and pack them as f32x2 lanes
        const ull AY = pack2(__shfl_sync(0xffffffffu, cy, 0), __shfl_sync(0xffffffffu, cy, 0));
        const ull AW = pack2(__shfl_sync(0xffffffffu, cw, 0), __shfl_sync(0xffffffffu, cw, 0));
        const ull BX = pack2(__shfl_sync(0xffffffffu, cx, 1), __shfl_sync(0xffffffffu, cx, 1));
        const ull BY = pack2(__shfl_sync(0xffffffffu, cy, 1), __shfl_sync(0xffffffffu, cy, 1));
        const ull PY = pack2(__shfl_sync(0xffffffffu, cy, 3), __shfl_sync(0xffffffffu, cy, 3));
        const ull PZ = pack2(__shfl_sync(0xffffffffu, cz, 3), __shfl_sync(0xffffffffu, cz, 3));
        const ull PW = pack2(__shfl_sync(0xffffffffu, cw, 3), __shfl_sync(0xffffffffu, cw, 3));
        const ull DY = pack2(__shfl_sync(0xffffffffu, cy, 4), __shfl_sync(0xffffffffu, cy, 4));
        const ull DW = pack2(__shfl_sync(0xffffffffu, cw, 4), __shfl_sync(0xffffffffu, cw, 4));
        const ull MAGIC  = pack2(MAGIC_RND, MAGIC_RND);
        const ull NMAGIC = pack2(-MAGIC_RND, -MAGIC_RND);
        const ull NEG1   = pack2(-1.0f, -1.0f);
        const ull TWOPI2 = pack2(TWO_PI, TWO_PI);

        const float4 x4 = __ldg(reinterpret_cast<const float4*>(x + i0));
        const float  xr[ROWS] = {x4.x, x4.y, x4.z, x4.w};

        const float4 y4 = __ldg(y4p + t);
        const ull Yp[2]  = {pack2(y4.x, y4.y), pack2(y4.z, y4.w)};
        const ull NYp[2] = {pack2(-y4.x, -y4.y), pack2(-y4.z, -y4.w)};

#pragma unroll
        for (int rr = 0; rr < ROWS; ++rr) {
            const float xi = xr[rr];
            const ull X2 = pack2(xi, xi);
            float r[4];
#pragma unroll
            for (int p = 0; p < 2; ++p) {
                ull D  = add2(X2, NYp[p]);                 // xi - yj (pair)
                ull D2 = mul2(D, D);
                ull A1 = fma2(AY, D2, AW);
                float a1l, a1h; unpack2(A1, a1l, a1h);
                float k1l = ex2_fast(a1l), k1h = ex2_fast(a1h);

                ull P  = mul2(X2, Yp[p]);
                ull K2 = fma2(BX, P, BY);

                ull H  = mul2(D, PZ);
                ull T  = add2(H, MAGIC);
                ull R  = add2(T, NMAGIC);
                ull F  = fma2(R, NEG1, H);                 // frac in [-0.5,0.5]
                ull FS = mul2(F, TWOPI2);
                float fl, fh; unpack2(FS, fl, fh);
                float sl = sin_fast(fl), sh = sin_fast(fh);
                ull S  = pack2(sl, sh);
                ull SP = mul2(S, PY);
                ull A3 = fma2(SP, S, PW);
                float a3l, a3h; unpack2(A3, a3l, a3h);
                float k3l = ex2_fast(a3l), k3h = ex2_fast(a3h);

                ull A4 = fma2(DY, D2, DW);
                float a4l, a4h; unpack2(A4, a4l, a4h);
                float k4l = ex2_fast(a4l), k4h = ex2_fast(a4h);

                ull M   = mul2(pack2(k1l, k1h), K2);
                ull S1  = add2(pack2(k4l, k4h), pack2(k3l, k3h));
                ull OUT = add2(S1, M);
                unpack2(OUT, r[2 * p], r[2 * p + 1]);
            }
            float4* o4p = reinterpret_cast<float4*>(out + (size_t)(i0 + rr) * d2);
            o4p[t] = make_float4(r[0], r[1], r[2], r[3]);
        }
        return;
    }

    // ---- generic interpreter fallback (uniform across the whole grid) ----
    __shared__ int    s_op[MAX_NODES];
    __shared__ float4 s_c[MAX_NODES];
    __shared__ int    s_meta[1];
    if (t == 0) compile_prog(pe, pl, params, s_op, s_c, s_meta);
    __syncthreads();

    const int n = s_meta[0];
    for (int rr = 0; rr < ROWS; ++rr) {
        const int i = i0 + rr;
        if (i >= d1) break;
        const float xi = __ldg(x + i);
        float4* o4p = reinterpret_cast<float4*>(out + (size_t)i * d2);
        for (int c = t; c < qcols; c += blockDim.x) {
            const float4 y4 = __ldg(y4p + c);
            float yv[4] = {y4.x, y4.y, y4.z, y4.w};
            float dx[4];
#pragma unroll
            for (int l = 0; l < 4; ++l) dx[l] = xi - yv[l];

            float st[4][4];
#pragma unroll
            for (int l = 0; l < 4; ++l) st[0][l] = 0.0f;
            int ptr = 0;
            for (int nn = 0; nn < n; ++nn) {
                const int    op = s_op[nn];
                const float4 cc = s_c[nn];
                if (op >= NUM_ATOMS) {
                    if (op == NUM_ATOMS) {
#pragma unroll
                        for (int l = 0; l < 4; ++l)
                            st[ptr - 2][l] = st[ptr - 1][l] + st[ptr - 2][l];
                    } else {
#pragma unroll
                        for (int l = 0; l < 4; ++l)
                            st[ptr - 2][l] = st[ptr - 1][l] * st[ptr - 2][l];
                    }
                    --ptr;
                } else if (op == 0) {
#pragma unroll
                    for (int l = 0; l < 4; ++l)
                        st[ptr][l] = cc.x * ex2_fast(cc.y * dx[l] * dx[l]);
                    ++ptr;
                } else if (op == 1) {
#pragma unroll
                    for (int l = 0; l < 4; ++l)
                        st[ptr][l] = fmaf(cc.x, xi * yv[l], cc.y);
                    ++ptr;
                } else {
#pragma unroll
                    for (int l = 0; l < 4; ++l) {
                        float s = sin2pi_frac(dx[l] * cc.z);
                        st[ptr][l] = cc.x * ex2_fast(cc.y * s * s);
                    }
                    ++ptr;
                }
            }
            o4p[c] = make_float4(st[0][0], st[0][1], st[0][2], st[0][3]);
        }
    }
}

// Scalar fallback for d2 not divisible by 4 (not expected in this bench).
__global__ void tree_scalar_kernel(const float* __restrict__ x,
                                   const float* __restrict__ y,
                                   float* __restrict__ out,
                                   int d1, int d2,
                                   const int* __restrict__ pe,
                                   const int* __restrict__ pl,
                                   const float* __restrict__ params) {
    __shared__ int    s_op[MAX_NODES];
    __shared__ float4 s_c[MAX_NODES];
    __shared__ int    s_meta[1];
    if (threadIdx.x == 0) compile_prog(pe, pl, params, s_op, s_c, s_meta);
    __syncthreads();

    long idx = (long)blockIdx.x * blockDim.x + threadIdx.x;
    long total = (long)d1 * d2;
    if (idx >= total) return;
    int i = (int)(idx / d2);
    int j = (int)(idx - (long)i * d2);
    float xi = x[i], yj = y[j];
    float dx = xi - yj;
    float st[4] = {0.f, 0.f, 0.f, 0.f};
    int ptr = 0;
    const int n = s_meta[0];
    for (int nn = 0; nn < n; ++nn) {
        const int    op = s_op[nn];
        const float4 c  = s_c[nn];
        if (op >= NUM_ATOMS) {
            float v = (op == NUM_ATOMS) ? (st[ptr - 1] + st[ptr - 2])
                                        : (st[ptr - 1] * st[ptr - 2]);
            st[ptr - 2] = v; --ptr;
        } else if (op == 0) {
            st[ptr++] = c.x * ex2_fast(c.y * dx * dx);
        } else if (op == 1) {
            st[ptr++] = fmaf(c.x, xi * yj, c.y);
        } else {
            float s = sin2pi_frac(dx * c.z);
            st[ptr++] = c.x * ex2_fast(c.y * s * s);
        }
    }
    out[idx] = st[0];
}

extern "C" void kernel_launch(void* const* d_in, const int* in_sizes, int n_in,
                              void* d_out, int out_size) {
    const float* x      = (const float*)d_in[0];
    const float* y      = (const float*)d_in[1];
    const int*   pe     = (const int*)d_in[2];
    const int*   pl     = (const int*)d_in[3];
    const float* params = (const float*)d_in[5];
    float*       out    = (float*)d_out;

    const int d1 = in_sizes[0];
    const int d2 = in_sizes[1];

    if ((d2 & 3) == 0 && (d1 % ROWS) == 0 && (d2 >> 2) == 512) {
        tree_fused_kernel<<<d1 / ROWS, 512>>>(x, y, out, d1, d2, pe, pl, params);
    } else if ((d2 & 3) == 0 && (d1 % ROWS) == 0 && (d2 >> 2) <= 1024) {
        tree_fused_kernel<<<d1 / ROWS, (d2 >> 2)>>>(x, y, out, d1, d2, pe, pl, params);
    } else {
        long total = (long)d1 * d2;
        int blocks = (int)((total + 255) / 256);
        tree_scalar_kernel<<<blocks, 256>>>(x, y, out, d1, d2, pe, pl, params);
    }
}